// round 1
// baseline (speedup 1.0000x reference)
#include <cuda_runtime.h>
#include <cuda_bf16.h>
#include <math.h>

// Problem constants
#define BB 2
#define TT 2048
#define CC 2048
#define HH 32
#define HKV 8
#define DD 64
#define MROWS (BB*TT)          // 4096
#define NQKV 3072              // H*D + 2*HKV*D

// Scratch (device globals: allocation-free per harness rules)
__device__ float g_qkv[MROWS * NQKV];          // [m][3072]  q|k|v
__device__ float g_q[BB * HH * TT * DD];       // [b][h][t][d]  (RoPE'd)
__device__ float g_k[BB * HKV * TT * DD];      // [b][hk][t][d] (RoPE'd)
__device__ float g_y[MROWS * CC];              // attention out [b][t][h*64+d]
__device__ float g_ct[TT * 32];                // cos table [t][freq]
__device__ float g_st[TT * 32];                // sin table [t][freq]

// ---------------------------------------------------------------------------
// SGEMM: C[m][n] = sum_k A[m][k] * B[n][k]   (both row-major, K contiguous)
// 128x128 block, BK=8, 256 threads, 8x8 per thread.
// M, N multiples of 128; K multiple of 8 (all true here).
// ---------------------------------------------------------------------------
__global__ __launch_bounds__(256)
void sgemm_tn(const float* __restrict__ A, const float* __restrict__ B,
              float* __restrict__ C, int K, int ldc)
{
    __shared__ float As[8][128];
    __shared__ float Bs[8][128];

    const int tid = threadIdx.x;
    const int tx = tid & 15, ty = tid >> 4;
    const int bm = blockIdx.y * 128, bn = blockIdx.x * 128;
    const int lrow = tid >> 1;
    const int lcol = (tid & 1) * 4;

    const float* Ap = A + (size_t)(bm + lrow) * K + lcol;
    const float* Bp = B + (size_t)(bn + lrow) * K + lcol;

    float acc[8][8];
#pragma unroll
    for (int i = 0; i < 8; i++)
#pragma unroll
        for (int j = 0; j < 8; j++) acc[i][j] = 0.f;

    for (int k0 = 0; k0 < K; k0 += 8) {
        float4 av = *(const float4*)(Ap + k0);
        float4 bv = *(const float4*)(Bp + k0);
        As[lcol + 0][lrow] = av.x; As[lcol + 1][lrow] = av.y;
        As[lcol + 2][lrow] = av.z; As[lcol + 3][lrow] = av.w;
        Bs[lcol + 0][lrow] = bv.x; Bs[lcol + 1][lrow] = bv.y;
        Bs[lcol + 2][lrow] = bv.z; Bs[lcol + 3][lrow] = bv.w;
        __syncthreads();
#pragma unroll
        for (int kk = 0; kk < 8; kk++) {
            float a[8], b[8];
            *(float4*)&a[0] = *(const float4*)&As[kk][ty * 8];
            *(float4*)&a[4] = *(const float4*)&As[kk][ty * 8 + 4];
            *(float4*)&b[0] = *(const float4*)&Bs[kk][tx * 8];
            *(float4*)&b[4] = *(const float4*)&Bs[kk][tx * 8 + 4];
#pragma unroll
            for (int i = 0; i < 8; i++)
#pragma unroll
                for (int j = 0; j < 8; j++) acc[i][j] += a[i] * b[j];
        }
        __syncthreads();
    }

    float* Cp = C + (size_t)(bm + ty * 8) * ldc + bn + tx * 8;
#pragma unroll
    for (int i = 0; i < 8; i++) {
        *(float4*)(Cp + (size_t)i * ldc)     = make_float4(acc[i][0], acc[i][1], acc[i][2], acc[i][3]);
        *(float4*)(Cp + (size_t)i * ldc + 4) = make_float4(acc[i][4], acc[i][5], acc[i][6], acc[i][7]);
    }
}

// ---------------------------------------------------------------------------
// RoPE cos/sin table: ct[t*32+j] = cos(pos[t] * theta^(-j/32)), same for sin.
// Computed in double so the table is more accurate than the fp32 reference.
// ---------------------------------------------------------------------------
__global__ void rope_tab(const int* __restrict__ pos,
                         float* __restrict__ ct, float* __restrict__ st)
{
    int idx = blockIdx.x * blockDim.x + threadIdx.x;
    if (idx >= TT * 32) return;
    int t = idx >> 5, j = idx & 31;
    double ang = (double)pos[t] * pow(10000.0, -(double)j / 32.0);
    double s, c;
    sincos(ang, &s, &c);
    ct[idx] = (float)c;
    st[idx] = (float)s;
}

// ---------------------------------------------------------------------------
// RoPE + reshape: qkv tmp [m][3072] -> Q[b][h][t][d], K[b][hk][t][d]
// out[d]    = x[d]  * cos(f[d/2])      - x[d+32] * sin(f[d/2])        (d < 32)
// out[d+32] = x[d+32]*cos(f[d/2 + 16]) + x[d]    * sin(f[d/2 + 16])
// ---------------------------------------------------------------------------
__global__ void rope_reshape(const float* __restrict__ qkv,
                             const float* __restrict__ ct, const float* __restrict__ st,
                             float* __restrict__ Qr, float* __restrict__ Kr)
{
    const int PPT = (HH + HKV) * 32;   // 1280 rotation pairs per (b,t)
    int idx = blockIdx.x * blockDim.x + threadIdx.x;
    if (idx >= BB * TT * PPT) return;
    int m = idx / PPT;
    int r = idx - m * PPT;
    int head = r >> 5, dp = r & 31;
    int b = m / TT, t = m - b * TT;

    const float* row = qkv + (size_t)m * NQKV;
    float x0, x1;
    float* dst;
    if (head < HH) {
        x0 = row[head * 64 + dp];
        x1 = row[head * 64 + dp + 32];
        dst = Qr + ((size_t)(b * HH + head) * TT + t) * 64;
    } else {
        int hk = head - HH;
        x0 = row[2048 + hk * 64 + dp];
        x1 = row[2048 + hk * 64 + dp + 32];
        dst = Kr + ((size_t)(b * HKV + hk) * TT + t) * 64;
    }
    int j = dp >> 1;
    float c1 = ct[t * 32 + j],      s1 = st[t * 32 + j];
    float c2 = ct[t * 32 + j + 16], s2 = st[t * 32 + j + 16];
    dst[dp]      = x0 * c1 - x1 * s1;
    dst[dp + 32] = x1 * c2 + x0 * s2;
}

// ---------------------------------------------------------------------------
// Flash attention (fp32, online softmax). One block per (q-tile 64, head, b).
// Q/K pre-RoPE'd in [b][h][t][d]; V read straight out of qkv tmp (stride 3072).
// Output written as [b][t][h*64+d] so the final GEMM is a plain row-major GEMM.
// ---------------------------------------------------------------------------
#define FPAD 68
#define FLASH_SMEM ((4 * 64 * FPAD + 128) * 4)

__global__ __launch_bounds__(256)
void flash_attn(const float* __restrict__ Q, const float* __restrict__ K,
                const float* __restrict__ Vg, float* __restrict__ Y)
{
    extern __shared__ float sm[];
    float* Qs   = sm;                  // [64][FPAD]
    float* Ks   = Qs + 64 * FPAD;
    float* Vs   = Ks + 64 * FPAD;
    float* Ps   = Vs + 64 * FPAD;
    float* rfac = Ps + 64 * FPAD;      // [64]
    float* rowl = rfac + 64;           // [64]

    const int tid = threadIdx.x;
    const int tx = tid & 15, ty = tid >> 4;
    const int qt = blockIdx.x, h = blockIdx.y, b = blockIdx.z;
    const int hk = h >> 2;             // GQA: repeat_interleave -> h // 4
    const int qbase = qt * 64;
    const float scale = 0.125f;        // 1/sqrt(64)

    // Load Q tile -> Qs[m][d]
    {
        int m = tid >> 2, d0 = (tid & 3) * 16;
        const float* src = Q + (((size_t)(b * HH + h) * TT) + qbase + m) * 64 + d0;
        float4* dst = (float4*)&Qs[m * FPAD + d0];
#pragma unroll
        for (int i = 0; i < 4; i++) dst[i] = ((const float4*)src)[i];
    }

    float Oacc[4][4];
#pragma unroll
    for (int i = 0; i < 4; i++)
#pragma unroll
        for (int j = 0; j < 4; j++) Oacc[i][j] = 0.f;

    float m_run = -1e30f, l_run = 0.f;
    const int r = tid >> 2, part = tid & 3;   // softmax: 4 threads per row

    for (int jt = 0; jt <= qt; jt++) {
        const int kbase = jt * 64;
        __syncthreads();   // protect Ks/Vs/Ps from previous iteration's readers
        // Load K, V tiles
        {
            int n = tid >> 2, d0 = (tid & 3) * 16;
            const float* ks = K + (((size_t)(b * HKV + hk) * TT) + kbase + n) * 64 + d0;
            const float* vs = Vg + ((size_t)(b * TT + kbase + n)) * NQKV + hk * 64 + d0;
            float4* kd = (float4*)&Ks[n * FPAD + d0];
            float4* vd = (float4*)&Vs[n * FPAD + d0];
#pragma unroll
            for (int i = 0; i < 4; i++) {
                kd[i] = ((const float4*)ks)[i];
                vd[i] = ((const float4*)vs)[i];
            }
        }
        __syncthreads();

        // S = Q K^T ; thread covers rows ty*4..+3, cols {tx, tx+16, tx+32, tx+48}
        float S[4][4];
#pragma unroll
        for (int i = 0; i < 4; i++)
#pragma unroll
            for (int j = 0; j < 4; j++) S[i][j] = 0.f;
#pragma unroll
        for (int d0 = 0; d0 < 64; d0 += 4) {
            float qv[4][4], kv[4][4];
#pragma unroll
            for (int i = 0; i < 4; i++)
                *(float4*)qv[i] = *(const float4*)&Qs[(ty * 4 + i) * FPAD + d0];
#pragma unroll
            for (int j = 0; j < 4; j++)
                *(float4*)kv[j] = *(const float4*)&Ks[(tx + 16 * j) * FPAD + d0];
#pragma unroll
            for (int i = 0; i < 4; i++)
#pragma unroll
                for (int j = 0; j < 4; j++)
                    S[i][j] += qv[i][0] * kv[j][0] + qv[i][1] * kv[j][1]
                             + qv[i][2] * kv[j][2] + qv[i][3] * kv[j][3];
        }

        // Scale, causal-mask (diagonal tile only), store to Ps
        const bool diag = (jt == qt);
#pragma unroll
        for (int i = 0; i < 4; i++) {
            int qi = qbase + ty * 4 + i;
#pragma unroll
            for (int j = 0; j < 4; j++) {
                int kj = kbase + tx + 16 * j;
                float v = S[i][j] * scale;
                if (diag && kj > qi) v = -1e30f;
                Ps[(ty * 4 + i) * FPAD + tx + 16 * j] = v;
            }
        }
        __syncthreads();

        // Online softmax: 4 threads per row, butterfly within lane-quad
        {
            float* prow = &Ps[r * FPAD + part * 16];
            float tmax = -1e30f;
#pragma unroll
            for (int c = 0; c < 16; c++) tmax = fmaxf(tmax, prow[c]);
            tmax = fmaxf(tmax, __shfl_xor_sync(0xffffffffu, tmax, 1));
            tmax = fmaxf(tmax, __shfl_xor_sync(0xffffffffu, tmax, 2));
            float newm = fmaxf(m_run, tmax);
            float psum = 0.f;
#pragma unroll
            for (int c = 0; c < 16; c++) {
                float p = __expf(prow[c] - newm);
                prow[c] = p;
                psum += p;
            }
            psum += __shfl_xor_sync(0xffffffffu, psum, 1);
            psum += __shfl_xor_sync(0xffffffffu, psum, 2);
            float rf = __expf(m_run - newm);
            l_run = l_run * rf + psum;
            m_run = newm;
            if (part == 0) { rfac[r] = rf; rowl[r] = l_run; }
        }
        __syncthreads();

        // Rescale O, then O += P V  (thread covers rows ty*4..+3, cols tx*4..+3)
#pragma unroll
        for (int i = 0; i < 4; i++) {
            float rf = rfac[ty * 4 + i];
#pragma unroll
            for (int j = 0; j < 4; j++) Oacc[i][j] *= rf;
        }
#pragma unroll
        for (int n0 = 0; n0 < 64; n0 += 4) {
            float pv[4][4], vv[4][4];
#pragma unroll
            for (int i = 0; i < 4; i++)
                *(float4*)pv[i] = *(const float4*)&Ps[(ty * 4 + i) * FPAD + n0];
#pragma unroll
            for (int s = 0; s < 4; s++)
                *(float4*)vv[s] = *(const float4*)&Vs[(n0 + s) * FPAD + tx * 4];
#pragma unroll
            for (int i = 0; i < 4; i++)
#pragma unroll
                for (int j = 0; j < 4; j++)
                    Oacc[i][j] += pv[i][0] * vv[0][j] + pv[i][1] * vv[1][j]
                                + pv[i][2] * vv[2][j] + pv[i][3] * vv[3][j];
        }
    }
    __syncthreads();

    // Normalize and write out: Y[b][t][h*64 + d]
#pragma unroll
    for (int i = 0; i < 4; i++) {
        float inv = 1.0f / rowl[ty * 4 + i];
        float4 o = make_float4(Oacc[i][0] * inv, Oacc[i][1] * inv,
                               Oacc[i][2] * inv, Oacc[i][3] * inv);
        *(float4*)&Y[((size_t)(b * TT + qbase + ty * 4 + i)) * CC + h * 64 + tx * 4] = o;
    }
}

// ---------------------------------------------------------------------------
extern "C" void kernel_launch(void* const* d_in, const int* in_sizes, int n_in,
                              void* d_out, int out_size)
{
    const float* x  = (const float*)d_in[0];
    const float* Wq = (const float*)d_in[1];
    const float* Wk = (const float*)d_in[2];
    const float* Wv = (const float*)d_in[3];
    const float* Wc = (const float*)d_in[4];
    const int* pos  = (const int*)d_in[5];
    float* out = (float*)d_out;

    float *qkv, *q, *k, *y, *ct, *st;
    cudaGetSymbolAddress((void**)&qkv, g_qkv);
    cudaGetSymbolAddress((void**)&q,   g_q);
    cudaGetSymbolAddress((void**)&k,   g_k);
    cudaGetSymbolAddress((void**)&y,   g_y);
    cudaGetSymbolAddress((void**)&ct,  g_ct);
    cudaGetSymbolAddress((void**)&st,  g_st);

    dim3 blk(256);

    // QKV projections into the packed tmp buffer (ldc = 3072)
    sgemm_tn<<<dim3(CC / 128, MROWS / 128), blk>>>(x, Wq, qkv,        CC, NQKV);
    sgemm_tn<<<dim3(512 / 128, MROWS / 128), blk>>>(x, Wk, qkv + 2048, CC, NQKV);
    sgemm_tn<<<dim3(512 / 128, MROWS / 128), blk>>>(x, Wv, qkv + 2560, CC, NQKV);

    // RoPE tables + apply RoPE / reshape for Q, K
    rope_tab<<<(TT * 32 + 255) / 256, 256>>>(pos, ct, st);
    rope_reshape<<<(BB * TT * (HH + HKV) * 32 + 255) / 256, 256>>>(qkv, ct, st, q, k);

    // Flash attention
    cudaFuncSetAttribute(flash_attn, cudaFuncAttributeMaxDynamicSharedMemorySize, FLASH_SMEM);
    flash_attn<<<dim3(TT / 64, HH, BB), blk, FLASH_SMEM>>>(q, k, qkv + 2560, y);

    // Output projection
    sgemm_tn<<<dim3(CC / 128, MROWS / 128), blk>>>(y, Wc, out, CC, CC);
}

// round 3
// speedup vs baseline: 1.6714x; 1.6714x over previous
#include <cuda_runtime.h>
#include <cuda_bf16.h>
#include <cstdint>
#include <math.h>

// Problem constants
#define BB 2
#define TT 2048
#define CC 2048
#define HH 32
#define HKV 8
#define DD 64
#define MROWS (BB*TT)          // 4096
#define NQKV 3072              // H*D + 2*HKV*D

// Scratch (device globals: allocation-free per harness rules)
__device__ float g_qkv[MROWS * NQKV];          // [m][3072]  q|k|v
__device__ float g_q[BB * HH * TT * DD];       // [b][h][t][d]  (RoPE'd)
__device__ float g_k[BB * HKV * TT * DD];      // [b][hk][t][d] (RoPE'd)
__device__ float g_y[MROWS * CC];              // attention out [b][t][h*64+d]
__device__ float g_ct[TT * 32];                // cos table [t][freq]
__device__ float g_st[TT * 32];                // sin table [t][freq]

// ---------------------------------------------------------------------------
// tf32 helpers
// ---------------------------------------------------------------------------
__device__ __forceinline__ uint32_t f2tf(float f) {
    uint32_t r;
    asm("cvt.rna.tf32.f32 %0, %1;" : "=r"(r) : "f"(f));
    return r;
}

__device__ __forceinline__ void mma_tf32(float* c,
                                         uint32_t a0, uint32_t a1, uint32_t a2, uint32_t a3,
                                         uint32_t b0, uint32_t b1) {
    asm volatile(
        "mma.sync.aligned.m16n8k8.row.col.f32.tf32.tf32.f32 "
        "{%0,%1,%2,%3}, {%4,%5,%6,%7}, {%8,%9}, {%0,%1,%2,%3};"
        : "+f"(c[0]), "+f"(c[1]), "+f"(c[2]), "+f"(c[3])
        : "r"(a0), "r"(a1), "r"(a2), "r"(a3), "r"(b0), "r"(b1));
}

// ---------------------------------------------------------------------------
// tf32 tensor-core GEMM body: C[m][n] = sum_k A[m][k] * B[n][k]
// 128x128x16 block tile, 256 threads (8 warps, 4x2), warp tile 32x64.
// Smem row stride 20 floats -> conflict-free mma fragment loads.
// ---------------------------------------------------------------------------
#define SROW 20

__device__ __forceinline__ void gemm_body(const float* __restrict__ A,
                                          const float* __restrict__ B,
                                          float* __restrict__ C,
                                          int K, int ldc, int bm, int bn)
{
    __shared__ uint32_t As[128 * SROW];
    __shared__ uint32_t Bs[128 * SROW];

    const int tid = threadIdx.x;
    const int lane = tid & 31, w = tid >> 5;
    const int wm = w >> 1, wn = w & 1;     // warp grid 4x2
    const int g = lane >> 2, tg = lane & 3;
    const int lr = tid >> 1;               // 0..127
    const int lc = (tid & 1) * 8;          // 0 or 8

    const float* Ap = A + (size_t)(bm + lr) * K + lc;
    const float* Bp = B + (size_t)(bn + lr) * K + lc;

    float acc[16][4];
#pragma unroll
    for (int i = 0; i < 16; i++)
#pragma unroll
        for (int j = 0; j < 4; j++) acc[i][j] = 0.f;

    const int nt = K / 16;

    float4 ra0 = *(const float4*)(Ap);
    float4 ra1 = *(const float4*)(Ap + 4);
    float4 rb0 = *(const float4*)(Bp);
    float4 rb1 = *(const float4*)(Bp + 4);

    uint32_t* ap = &As[lr * SROW + lc];
    uint32_t* bp = &Bs[lr * SROW + lc];

    for (int kt = 0; kt < nt; kt++) {
        // store current tile (convert to tf32 with round-to-nearest)
        ap[0] = f2tf(ra0.x); ap[1] = f2tf(ra0.y); ap[2] = f2tf(ra0.z); ap[3] = f2tf(ra0.w);
        ap[4] = f2tf(ra1.x); ap[5] = f2tf(ra1.y); ap[6] = f2tf(ra1.z); ap[7] = f2tf(ra1.w);
        bp[0] = f2tf(rb0.x); bp[1] = f2tf(rb0.y); bp[2] = f2tf(rb0.z); bp[3] = f2tf(rb0.w);
        bp[4] = f2tf(rb1.x); bp[5] = f2tf(rb1.y); bp[6] = f2tf(rb1.z); bp[7] = f2tf(rb1.w);
        __syncthreads();

        // prefetch next tile to registers (hides LDG under the mma block)
        if (kt + 1 < nt) {
            const float* An = Ap + (kt + 1) * 16;
            const float* Bn = Bp + (kt + 1) * 16;
            ra0 = *(const float4*)(An);
            ra1 = *(const float4*)(An + 4);
            rb0 = *(const float4*)(Bn);
            rb1 = *(const float4*)(Bn + 4);
        }

#pragma unroll
        for (int kk = 0; kk < 16; kk += 8) {
            uint32_t af[2][4], bf[8][2];
#pragma unroll
            for (int mi = 0; mi < 2; mi++) {
                int r = wm * 32 + mi * 16 + g;
                af[mi][0] = As[r * SROW + kk + tg];
                af[mi][1] = As[(r + 8) * SROW + kk + tg];
                af[mi][2] = As[r * SROW + kk + tg + 4];
                af[mi][3] = As[(r + 8) * SROW + kk + tg + 4];
            }
#pragma unroll
            for (int ni = 0; ni < 8; ni++) {
                int n = wn * 64 + ni * 8 + g;
                bf[ni][0] = Bs[n * SROW + kk + tg];
                bf[ni][1] = Bs[n * SROW + kk + tg + 4];
            }
#pragma unroll
            for (int mi = 0; mi < 2; mi++)
#pragma unroll
                for (int ni = 0; ni < 8; ni++)
                    mma_tf32(acc[mi * 8 + ni],
                             af[mi][0], af[mi][1], af[mi][2], af[mi][3],
                             bf[ni][0], bf[ni][1]);
        }
        __syncthreads();
    }

    // epilogue: c0,c1 at (row, col..col+1); c2,c3 at (row+8, ...)
#pragma unroll
    for (int mi = 0; mi < 2; mi++) {
        int row = bm + wm * 32 + mi * 16 + g;
#pragma unroll
        for (int ni = 0; ni < 8; ni++) {
            int col = bn + wn * 64 + ni * 8 + tg * 2;
            const float* a = acc[mi * 8 + ni];
            *(float2*)&C[(size_t)row * ldc + col]       = make_float2(a[0], a[1]);
            *(float2*)&C[(size_t)(row + 8) * ldc + col] = make_float2(a[2], a[3]);
        }
    }
}

// Fused QKV projection: one launch covers Wq (16 n-tiles), Wk (4), Wv (4).
__global__ __launch_bounds__(256)
void qkv_gemm(const float* __restrict__ x, const float* __restrict__ Wq,
              const float* __restrict__ Wk, const float* __restrict__ Wv,
              float* __restrict__ qkv)
{
    int nx = blockIdx.x;
    const float* B;
    int bn, coff;
    if (nx < 16)      { B = Wq; bn = nx * 128;        coff = 0; }
    else if (nx < 20) { B = Wk; bn = (nx - 16) * 128; coff = 2048; }
    else              { B = Wv; bn = (nx - 20) * 128; coff = 2560; }
    gemm_body(x, B, qkv + coff, CC, NQKV, blockIdx.y * 128, bn);
}

// Output projection: out = y @ Wc^T
__global__ __launch_bounds__(256)
void proj_gemm(const float* __restrict__ y, const float* __restrict__ Wc,
               float* __restrict__ out)
{
    gemm_body(y, Wc, out, CC, CC, blockIdx.y * 128, blockIdx.x * 128);
}

// ---------------------------------------------------------------------------
// RoPE cos/sin table (double precision for accuracy)
// ---------------------------------------------------------------------------
__global__ void rope_tab(const int* __restrict__ pos,
                         float* __restrict__ ct, float* __restrict__ st)
{
    int idx = blockIdx.x * blockDim.x + threadIdx.x;
    if (idx >= TT * 32) return;
    int t = idx >> 5, j = idx & 31;
    double ang = (double)pos[t] * pow(10000.0, -(double)j / 32.0);
    double s, c;
    sincos(ang, &s, &c);
    ct[idx] = (float)c;
    st[idx] = (float)s;
}

// ---------------------------------------------------------------------------
// RoPE + reshape: qkv tmp [m][3072] -> Q[b][h][t][d], K[b][hk][t][d]
// ---------------------------------------------------------------------------
__global__ void rope_reshape(const float* __restrict__ qkv,
                             const float* __restrict__ ct, const float* __restrict__ st,
                             float* __restrict__ Qr, float* __restrict__ Kr)
{
    const int PPT = (HH + HKV) * 32;   // 1280 rotation pairs per (b,t)
    int idx = blockIdx.x * blockDim.x + threadIdx.x;
    if (idx >= BB * TT * PPT) return;
    int m = idx / PPT;
    int r = idx - m * PPT;
    int head = r >> 5, dp = r & 31;
    int b = m / TT, t = m - b * TT;

    const float* row = qkv + (size_t)m * NQKV;
    float x0, x1;
    float* dst;
    if (head < HH) {
        x0 = row[head * 64 + dp];
        x1 = row[head * 64 + dp + 32];
        dst = Qr + ((size_t)(b * HH + head) * TT + t) * 64;
    } else {
        int hk = head - HH;
        x0 = row[2048 + hk * 64 + dp];
        x1 = row[2048 + hk * 64 + dp + 32];
        dst = Kr + ((size_t)(b * HKV + hk) * TT + t) * 64;
    }
    int j = dp >> 1;
    float c1 = ct[t * 32 + j],      s1 = st[t * 32 + j];
    float c2 = ct[t * 32 + j + 16], s2 = st[t * 32 + j + 16];
    dst[dp]      = x0 * c1 - x1 * s1;
    dst[dp + 32] = x1 * c2 + x0 * s2;
}

// ---------------------------------------------------------------------------
// Flash attention (fp32, online softmax). One block per (q-tile 64, head, b).
// ---------------------------------------------------------------------------
#define FPAD 68
#define FLASH_SMEM ((4 * 64 * FPAD + 128) * 4)

__global__ __launch_bounds__(256)
void flash_attn(const float* __restrict__ Q, const float* __restrict__ K,
                const float* __restrict__ Vg, float* __restrict__ Y)
{
    extern __shared__ float sm[];
    float* Qs   = sm;                  // [64][FPAD]
    float* Ks   = Qs + 64 * FPAD;
    float* Vs   = Ks + 64 * FPAD;
    float* Ps   = Vs + 64 * FPAD;
    float* rfac = Ps + 64 * FPAD;      // [64]
    float* rowl = rfac + 64;           // [64]

    const int tid = threadIdx.x;
    const int tx = tid & 15, ty = tid >> 4;
    const int qt = blockIdx.x, h = blockIdx.y, b = blockIdx.z;
    const int hk = h >> 2;             // GQA: repeat_interleave -> h // 4
    const int qbase = qt * 64;
    const float scale = 0.125f;        // 1/sqrt(64)

    // Load Q tile -> Qs[m][d]
    {
        int m = tid >> 2, d0 = (tid & 3) * 16;
        const float* src = Q + (((size_t)(b * HH + h) * TT) + qbase + m) * 64 + d0;
        float4* dst = (float4*)&Qs[m * FPAD + d0];
#pragma unroll
        for (int i = 0; i < 4; i++) dst[i] = ((const float4*)src)[i];
    }

    float Oacc[4][4];
#pragma unroll
    for (int i = 0; i < 4; i++)
#pragma unroll
        for (int j = 0; j < 4; j++) Oacc[i][j] = 0.f;

    float m_run = -1e30f, l_run = 0.f;
    const int r = tid >> 2, part = tid & 3;   // softmax: 4 threads per row

    for (int jt = 0; jt <= qt; jt++) {
        const int kbase = jt * 64;
        __syncthreads();   // protect Ks/Vs/Ps from previous iteration's readers
        // Load K, V tiles
        {
            int n = tid >> 2, d0 = (tid & 3) * 16;
            const float* ks = K + (((size_t)(b * HKV + hk) * TT) + kbase + n) * 64 + d0;
            const float* vs = Vg + ((size_t)(b * TT + kbase + n)) * NQKV + hk * 64 + d0;
            float4* kd = (float4*)&Ks[n * FPAD + d0];
            float4* vd = (float4*)&Vs[n * FPAD + d0];
#pragma unroll
            for (int i = 0; i < 4; i++) {
                kd[i] = ((const float4*)ks)[i];
                vd[i] = ((const float4*)vs)[i];
            }
        }
        __syncthreads();

        // S = Q K^T ; thread covers rows ty*4..+3, cols {tx, tx+16, tx+32, tx+48}
        float S[4][4];
#pragma unroll
        for (int i = 0; i < 4; i++)
#pragma unroll
            for (int j = 0; j < 4; j++) S[i][j] = 0.f;
#pragma unroll
        for (int d0 = 0; d0 < 64; d0 += 4) {
            float qv[4][4], kv[4][4];
#pragma unroll
            for (int i = 0; i < 4; i++)
                *(float4*)qv[i] = *(const float4*)&Qs[(ty * 4 + i) * FPAD + d0];
#pragma unroll
            for (int j = 0; j < 4; j++)
                *(float4*)kv[j] = *(const float4*)&Ks[(tx + 16 * j) * FPAD + d0];
#pragma unroll
            for (int i = 0; i < 4; i++)
#pragma unroll
                for (int j = 0; j < 4; j++)
                    S[i][j] += qv[i][0] * kv[j][0] + qv[i][1] * kv[j][1]
                             + qv[i][2] * kv[j][2] + qv[i][3] * kv[j][3];
        }

        // Scale, causal-mask (diagonal tile only), store to Ps
        const bool diag = (jt == qt);
#pragma unroll
        for (int i = 0; i < 4; i++) {
            int qi = qbase + ty * 4 + i;
#pragma unroll
            for (int j = 0; j < 4; j++) {
                int kj = kbase + tx + 16 * j;
                float v = S[i][j] * scale;
                if (diag && kj > qi) v = -1e30f;
                Ps[(ty * 4 + i) * FPAD + tx + 16 * j] = v;
            }
        }
        __syncthreads();

        // Online softmax: 4 threads per row, butterfly within lane-quad
        {
            float* prow = &Ps[r * FPAD + part * 16];
            float tmax = -1e30f;
#pragma unroll
            for (int c = 0; c < 16; c++) tmax = fmaxf(tmax, prow[c]);
            tmax = fmaxf(tmax, __shfl_xor_sync(0xffffffffu, tmax, 1));
            tmax = fmaxf(tmax, __shfl_xor_sync(0xffffffffu, tmax, 2));
            float newm = fmaxf(m_run, tmax);
            float psum = 0.f;
#pragma unroll
            for (int c = 0; c < 16; c++) {
                float p = __expf(prow[c] - newm);
                prow[c] = p;
                psum += p;
            }
            psum += __shfl_xor_sync(0xffffffffu, psum, 1);
            psum += __shfl_xor_sync(0xffffffffu, psum, 2);
            float rf = __expf(m_run - newm);
            l_run = l_run * rf + psum;
            m_run = newm;
            if (part == 0) { rfac[r] = rf; rowl[r] = l_run; }
        }
        __syncthreads();

        // Rescale O, then O += P V  (thread covers rows ty*4..+3, cols tx*4..+3)
#pragma unroll
        for (int i = 0; i < 4; i++) {
            float rf = rfac[ty * 4 + i];
#pragma unroll
            for (int j = 0; j < 4; j++) Oacc[i][j] *= rf;
        }
#pragma unroll
        for (int n0 = 0; n0 < 64; n0 += 4) {
            float pv[4][4], vv[4][4];
#pragma unroll
            for (int i = 0; i < 4; i++)
                *(float4*)pv[i] = *(const float4*)&Ps[(ty * 4 + i) * FPAD + n0];
#pragma unroll
            for (int s = 0; s < 4; s++)
                *(float4*)vv[s] = *(const float4*)&Vs[(n0 + s) * FPAD + tx * 4];
#pragma unroll
            for (int i = 0; i < 4; i++)
#pragma unroll
                for (int j = 0; j < 4; j++)
                    Oacc[i][j] += pv[i][0] * vv[0][j] + pv[i][1] * vv[1][j]
                                + pv[i][2] * vv[2][j] + pv[i][3] * vv[3][j];
        }
    }
    __syncthreads();

    // Normalize and write out: Y[b][t][h*64 + d]
#pragma unroll
    for (int i = 0; i < 4; i++) {
        float inv = 1.0f / rowl[ty * 4 + i];
        float4 o = make_float4(Oacc[i][0] * inv, Oacc[i][1] * inv,
                               Oacc[i][2] * inv, Oacc[i][3] * inv);
        *(float4*)&Y[((size_t)(b * TT + qbase + ty * 4 + i)) * CC + h * 64 + tx * 4] = o;
    }
}

// ---------------------------------------------------------------------------
extern "C" void kernel_launch(void* const* d_in, const int* in_sizes, int n_in,
                              void* d_out, int out_size)
{
    const float* x  = (const float*)d_in[0];
    const float* Wq = (const float*)d_in[1];
    const float* Wk = (const float*)d_in[2];
    const float* Wv = (const float*)d_in[3];
    const float* Wc = (const float*)d_in[4];
    const int* pos  = (const int*)d_in[5];
    float* out = (float*)d_out;

    float *qkv, *q, *k, *y, *ct, *st;
    cudaGetSymbolAddress((void**)&qkv, g_qkv);
    cudaGetSymbolAddress((void**)&q,   g_q);
    cudaGetSymbolAddress((void**)&k,   g_k);
    cudaGetSymbolAddress((void**)&y,   g_y);
    cudaGetSymbolAddress((void**)&ct,  g_ct);
    cudaGetSymbolAddress((void**)&st,  g_st);

    // Fused QKV projection (tf32 tensor cores), packed output ldc = 3072
    qkv_gemm<<<dim3(24, 32), 256>>>(x, Wq, Wk, Wv, qkv);

    // RoPE tables + apply RoPE / reshape for Q, K
    rope_tab<<<(TT * 32 + 255) / 256, 256>>>(pos, ct, st);
    rope_reshape<<<(BB * TT * (HH + HKV) * 32 + 255) / 256, 256>>>(qkv, ct, st, q, k);

    // Flash attention (fp32)
    cudaFuncSetAttribute(flash_attn, cudaFuncAttributeMaxDynamicSharedMemorySize, FLASH_SMEM);
    flash_attn<<<dim3(TT / 64, HH, BB), 256, FLASH_SMEM>>>(q, k, qkv + 2560, y);

    // Output projection (tf32 tensor cores)
    proj_gemm<<<dim3(16, 32), 256>>>(y, Wc, out);
}

// round 6
// speedup vs baseline: 2.4958x; 1.4932x over previous
#include <cuda_runtime.h>
#include <cuda_bf16.h>
#include <cstdint>
#include <math.h>

// Problem constants
#define BB 2
#define TT 2048
#define CC 2048
#define HH 32
#define HKV 8
#define DD 64
#define MROWS (BB*TT)          // 4096
#define NQKV 3072              // H*D + 2*HKV*D

// Scratch (device globals: allocation-free per harness rules)
__device__ float g_qkv[MROWS * NQKV];          // [m][3072]  q|k|v
__device__ float g_q[BB * HH * TT * DD];       // [b][h][t][d]  (RoPE'd)
__device__ float g_k[BB * HKV * TT * DD];      // [b][hk][t][d] (RoPE'd)
__device__ float g_y[MROWS * CC];              // attention out [b][t][h*64+d]
__device__ float g_ct[TT * 32];                // cos table [t][freq]
__device__ float g_st[TT * 32];                // sin table [t][freq]

// ---------------------------------------------------------------------------
// tf32 helpers
// ---------------------------------------------------------------------------
__device__ __forceinline__ uint32_t f2tf(float f) {
    uint32_t r;
    asm("cvt.rna.tf32.f32 %0, %1;" : "=r"(r) : "f"(f));
    return r;
}

__device__ __forceinline__ void mma_tf32(float* c,
                                         uint32_t a0, uint32_t a1, uint32_t a2, uint32_t a3,
                                         uint32_t b0, uint32_t b1) {
    asm volatile(
        "mma.sync.aligned.m16n8k8.row.col.f32.tf32.tf32.f32 "
        "{%0,%1,%2,%3}, {%4,%5,%6,%7}, {%8,%9}, {%0,%1,%2,%3};"
        : "+f"(c[0]), "+f"(c[1]), "+f"(c[2]), "+f"(c[3])
        : "r"(a0), "r"(a1), "r"(a2), "r"(a3), "r"(b0), "r"(b1));
}

// ---------------------------------------------------------------------------
// tf32 tensor-core GEMM body: C[m][n] = sum_k A[m][k] * B[n][k]
// 128x128x16 block tile, 256 threads (8 warps, 4x2), warp tile 32x64.
// ---------------------------------------------------------------------------
#define SROW 20

__device__ __forceinline__ void gemm_body(const float* __restrict__ A,
                                          const float* __restrict__ B,
                                          float* __restrict__ C,
                                          int K, int ldc, int bm, int bn)
{
    __shared__ uint32_t As[128 * SROW];
    __shared__ uint32_t Bs[128 * SROW];

    const int tid = threadIdx.x;
    const int lane = tid & 31, w = tid >> 5;
    const int wm = w >> 1, wn = w & 1;     // warp grid 4x2
    const int g = lane >> 2, tg = lane & 3;
    const int lr = tid >> 1;               // 0..127
    const int lc = (tid & 1) * 8;          // 0 or 8

    const float* Ap = A + (size_t)(bm + lr) * K + lc;
    const float* Bp = B + (size_t)(bn + lr) * K + lc;

    float acc[16][4];
#pragma unroll
    for (int i = 0; i < 16; i++)
#pragma unroll
        for (int j = 0; j < 4; j++) acc[i][j] = 0.f;

    const int nt = K / 16;

    float4 ra0 = *(const float4*)(Ap);
    float4 ra1 = *(const float4*)(Ap + 4);
    float4 rb0 = *(const float4*)(Bp);
    float4 rb1 = *(const float4*)(Bp + 4);

    uint32_t* ap = &As[lr * SROW + lc];
    uint32_t* bp = &Bs[lr * SROW + lc];

    for (int kt = 0; kt < nt; kt++) {
        ap[0] = f2tf(ra0.x); ap[1] = f2tf(ra0.y); ap[2] = f2tf(ra0.z); ap[3] = f2tf(ra0.w);
        ap[4] = f2tf(ra1.x); ap[5] = f2tf(ra1.y); ap[6] = f2tf(ra1.z); ap[7] = f2tf(ra1.w);
        bp[0] = f2tf(rb0.x); bp[1] = f2tf(rb0.y); bp[2] = f2tf(rb0.z); bp[3] = f2tf(rb0.w);
        bp[4] = f2tf(rb1.x); bp[5] = f2tf(rb1.y); bp[6] = f2tf(rb1.z); bp[7] = f2tf(rb1.w);
        __syncthreads();

        if (kt + 1 < nt) {
            const float* An = Ap + (kt + 1) * 16;
            const float* Bn = Bp + (kt + 1) * 16;
            ra0 = *(const float4*)(An);
            ra1 = *(const float4*)(An + 4);
            rb0 = *(const float4*)(Bn);
            rb1 = *(const float4*)(Bn + 4);
        }

#pragma unroll
        for (int kk = 0; kk < 16; kk += 8) {
            uint32_t af[2][4], bf[8][2];
#pragma unroll
            for (int mi = 0; mi < 2; mi++) {
                int r = wm * 32 + mi * 16 + g;
                af[mi][0] = As[r * SROW + kk + tg];
                af[mi][1] = As[(r + 8) * SROW + kk + tg];
                af[mi][2] = As[r * SROW + kk + tg + 4];
                af[mi][3] = As[(r + 8) * SROW + kk + tg + 4];
            }
#pragma unroll
            for (int ni = 0; ni < 8; ni++) {
                int n = wn * 64 + ni * 8 + g;
                bf[ni][0] = Bs[n * SROW + kk + tg];
                bf[ni][1] = Bs[n * SROW + kk + tg + 4];
            }
#pragma unroll
            for (int mi = 0; mi < 2; mi++)
#pragma unroll
                for (int ni = 0; ni < 8; ni++)
                    mma_tf32(acc[mi * 8 + ni],
                             af[mi][0], af[mi][1], af[mi][2], af[mi][3],
                             bf[ni][0], bf[ni][1]);
        }
        __syncthreads();
    }

#pragma unroll
    for (int mi = 0; mi < 2; mi++) {
        int row = bm + wm * 32 + mi * 16 + g;
#pragma unroll
        for (int ni = 0; ni < 8; ni++) {
            int col = bn + wn * 64 + ni * 8 + tg * 2;
            const float* a = acc[mi * 8 + ni];
            *(float2*)&C[(size_t)row * ldc + col]       = make_float2(a[0], a[1]);
            *(float2*)&C[(size_t)(row + 8) * ldc + col] = make_float2(a[2], a[3]);
        }
    }
}

// Fused QKV projection: one launch covers Wq (16 n-tiles), Wk (4), Wv (4).
__global__ __launch_bounds__(256)
void qkv_gemm(const float* __restrict__ x, const float* __restrict__ Wq,
              const float* __restrict__ Wk, const float* __restrict__ Wv,
              float* __restrict__ qkv)
{
    int nx = blockIdx.x;
    const float* B;
    int bn, coff;
    if (nx < 16)      { B = Wq; bn = nx * 128;        coff = 0; }
    else if (nx < 20) { B = Wk; bn = (nx - 16) * 128; coff = 2048; }
    else              { B = Wv; bn = (nx - 20) * 128; coff = 2560; }
    gemm_body(x, B, qkv + coff, CC, NQKV, blockIdx.y * 128, bn);
}

// Output projection: out = y @ Wc^T
__global__ __launch_bounds__(256)
void proj_gemm(const float* __restrict__ y, const float* __restrict__ Wc,
               float* __restrict__ out)
{
    gemm_body(y, Wc, out, CC, CC, blockIdx.y * 128, blockIdx.x * 128);
}

// ---------------------------------------------------------------------------
// RoPE cos/sin table (double precision for accuracy)
// ---------------------------------------------------------------------------
__global__ void rope_tab(const int* __restrict__ pos,
                         float* __restrict__ ct, float* __restrict__ st)
{
    int idx = blockIdx.x * blockDim.x + threadIdx.x;
    if (idx >= TT * 32) return;
    int t = idx >> 5, j = idx & 31;
    double ang = (double)pos[t] * pow(10000.0, -(double)j / 32.0);
    double s, c;
    sincos(ang, &s, &c);
    ct[idx] = (float)c;
    st[idx] = (float)s;
}

// ---------------------------------------------------------------------------
// RoPE + reshape: qkv tmp [m][3072] -> Q[b][h][t][d], K[b][hk][t][d]
// ---------------------------------------------------------------------------
__global__ void rope_reshape(const float* __restrict__ qkv,
                             const float* __restrict__ ct, const float* __restrict__ st,
                             float* __restrict__ Qr, float* __restrict__ Kr)
{
    const int PPT = (HH + HKV) * 32;   // 1280 rotation pairs per (b,t)
    int idx = blockIdx.x * blockDim.x + threadIdx.x;
    if (idx >= BB * TT * PPT) return;
    int m = idx / PPT;
    int r = idx - m * PPT;
    int head = r >> 5, dp = r & 31;
    int b = m / TT, t = m - b * TT;

    const float* row = qkv + (size_t)m * NQKV;
    float x0, x1;
    float* dst;
    if (head < HH) {
        x0 = row[head * 64 + dp];
        x1 = row[head * 64 + dp + 32];
        dst = Qr + ((size_t)(b * HH + head) * TT + t) * 64;
    } else {
        int hk = head - HH;
        x0 = row[2048 + hk * 64 + dp];
        x1 = row[2048 + hk * 64 + dp + 32];
        dst = Kr + ((size_t)(b * HKV + hk) * TT + t) * 64;
    }
    int j = dp >> 1;
    float c1 = ct[t * 32 + j],      s1 = st[t * 32 + j];
    float c2 = ct[t * 32 + j + 16], s2 = st[t * 32 + j + 16];
    dst[dp]      = x0 * c1 - x1 * s1;
    dst[dp + 32] = x1 * c2 + x0 * s2;
}

// ---------------------------------------------------------------------------
// Tensor-core flash attention (tf32 mma, fp32 softmax in registers).
// Block: 256 threads (8 warps). Q-tile 128 rows (16 per warp), KV-tile 64.
// Softmax running state in registers, replicated per lane-quad via shfl.
// P round-trips through per-warp-private smem (frag layout change only).
// ---------------------------------------------------------------------------
#define FS 68
#define FLASH_SMEM (384 * FS * 4)   // Qs 128 + Ks 64 + Vs 64 + Ps 128 rows

__global__ __launch_bounds__(256)
void flash_attn_tc(const float* __restrict__ Q, const float* __restrict__ K,
                   const float* __restrict__ Vg, float* __restrict__ Y)
{
    extern __shared__ uint32_t smu[];
    uint32_t* Qs = smu;                 // [128][FS]
    uint32_t* Ks = Qs + 128 * FS;       // [64][FS]
    uint32_t* Vs = Ks + 64 * FS;        // [64][FS]
    uint32_t* Ps = Vs + 64 * FS;        // [128][FS], rows w*16.. private per warp

    const int tid = threadIdx.x;
    const int lane = tid & 31, w = tid >> 5;
    const int g = lane >> 2, tg = lane & 3;
    const int qt = (gridDim.x - 1) - blockIdx.x;   // heavy blocks first
    const int h = blockIdx.y, b = blockIdx.z, hk = h >> 2;
    const int qbase = qt * 128;
    const float scale = 0.125f;

    // Load Q tile (128 x 64) -> Qs as tf32
    {
        int r = tid >> 1, c0 = (tid & 1) * 32;
        const float* src = Q + (((size_t)(b * HH + h) * TT) + qbase + r) * 64 + c0;
        uint32_t* dst = Qs + r * FS + c0;
#pragma unroll
        for (int i = 0; i < 8; i++) {
            float4 v = ((const float4*)src)[i];
            dst[4 * i + 0] = f2tf(v.x); dst[4 * i + 1] = f2tf(v.y);
            dst[4 * i + 2] = f2tf(v.z); dst[4 * i + 3] = f2tf(v.w);
        }
    }

    float Oc[8][4];
#pragma unroll
    for (int i = 0; i < 8; i++)
#pragma unroll
        for (int j = 0; j < 4; j++) Oc[i][j] = 0.f;

    float mrun0 = -1e30f, mrun1 = -1e30f, lrun0 = 0.f, lrun1 = 0.f;
    const int row0 = qbase + w * 16 + g;   // rows for c0/c1
    const int row1 = row0 + 8;             // rows for c2/c3
    const int slab = w * 16;

    const int nkv = 2 * qt + 2;
    for (int jt = 0; jt < nkv; jt++) {
        const int kbase = jt * 64;
        __syncthreads();
        // Load K, V tiles (64 x 64 each) as tf32
        {
            int r = tid >> 2, c0 = (tid & 3) * 16;
            const float* ks = K + (((size_t)(b * HKV + hk) * TT) + kbase + r) * 64 + c0;
            const float* vs = Vg + ((size_t)(b * TT + kbase + r)) * NQKV + hk * 64 + c0;
            uint32_t* kd = Ks + r * FS + c0;
            uint32_t* vd = Vs + r * FS + c0;
#pragma unroll
            for (int i = 0; i < 4; i++) {
                float4 kv4 = ((const float4*)ks)[i];
                float4 vv4 = ((const float4*)vs)[i];
                kd[4 * i + 0] = f2tf(kv4.x); kd[4 * i + 1] = f2tf(kv4.y);
                kd[4 * i + 2] = f2tf(kv4.z); kd[4 * i + 3] = f2tf(kv4.w);
                vd[4 * i + 0] = f2tf(vv4.x); vd[4 * i + 1] = f2tf(vv4.y);
                vd[4 * i + 2] = f2tf(vv4.z); vd[4 * i + 3] = f2tf(vv4.w);
            }
        }
        __syncthreads();

        // S = Q K^T : warp computes 16 x 64
        float Sc[8][4];
#pragma unroll
        for (int i = 0; i < 8; i++)
#pragma unroll
            for (int j = 0; j < 4; j++) Sc[i][j] = 0.f;
#pragma unroll
        for (int kk = 0; kk < 64; kk += 8) {
            uint32_t a0 = Qs[(slab + g) * FS + kk + tg];
            uint32_t a1 = Qs[(slab + g + 8) * FS + kk + tg];
            uint32_t a2 = Qs[(slab + g) * FS + kk + tg + 4];
            uint32_t a3 = Qs[(slab + g + 8) * FS + kk + tg + 4];
#pragma unroll
            for (int ni = 0; ni < 8; ni++) {
                uint32_t b0 = Ks[(ni * 8 + g) * FS + kk + tg];
                uint32_t b1 = Ks[(ni * 8 + g) * FS + kk + tg + 4];
                mma_tf32(Sc[ni], a0, a1, a2, a3, b0, b1);
            }
        }

        // scale + causal mask + row max
        const bool needmask = (kbase + 63) > (qbase + slab);
        float mx0 = -1e30f, mx1 = -1e30f;
#pragma unroll
        for (int ni = 0; ni < 8; ni++) {
            int c = kbase + ni * 8 + 2 * tg;
            float s0 = Sc[ni][0] * scale, s1 = Sc[ni][1] * scale;
            float s2 = Sc[ni][2] * scale, s3 = Sc[ni][3] * scale;
            if (needmask) {
                if (c     > row0) s0 = -1e30f;
                if (c + 1 > row0) s1 = -1e30f;
                if (c     > row1) s2 = -1e30f;
                if (c + 1 > row1) s3 = -1e30f;
            }
            Sc[ni][0] = s0; Sc[ni][1] = s1; Sc[ni][2] = s2; Sc[ni][3] = s3;
            mx0 = fmaxf(mx0, fmaxf(s0, s1));
            mx1 = fmaxf(mx1, fmaxf(s2, s3));
        }
        mx0 = fmaxf(mx0, __shfl_xor_sync(0xffffffffu, mx0, 1));
        mx0 = fmaxf(mx0, __shfl_xor_sync(0xffffffffu, mx0, 2));
        mx1 = fmaxf(mx1, __shfl_xor_sync(0xffffffffu, mx1, 1));
        mx1 = fmaxf(mx1, __shfl_xor_sync(0xffffffffu, mx1, 2));

        float nm0 = fmaxf(mrun0, mx0), nm1 = fmaxf(mrun1, mx1);
        float ps0 = 0.f, ps1 = 0.f;
#pragma unroll
        for (int ni = 0; ni < 8; ni++) {
            float p0 = __expf(Sc[ni][0] - nm0);
            float p1 = __expf(Sc[ni][1] - nm0);
            float p2 = __expf(Sc[ni][2] - nm1);
            float p3 = __expf(Sc[ni][3] - nm1);
            ps0 += p0 + p1; ps1 += p2 + p3;
            Ps[(slab + g) * FS + ni * 8 + 2 * tg]         = f2tf(p0);
            Ps[(slab + g) * FS + ni * 8 + 2 * tg + 1]     = f2tf(p1);
            Ps[(slab + g + 8) * FS + ni * 8 + 2 * tg]     = f2tf(p2);
            Ps[(slab + g + 8) * FS + ni * 8 + 2 * tg + 1] = f2tf(p3);
        }
        ps0 += __shfl_xor_sync(0xffffffffu, ps0, 1);
        ps0 += __shfl_xor_sync(0xffffffffu, ps0, 2);
        ps1 += __shfl_xor_sync(0xffffffffu, ps1, 1);
        ps1 += __shfl_xor_sync(0xffffffffu, ps1, 2);

        float rf0 = __expf(mrun0 - nm0), rf1 = __expf(mrun1 - nm1);
        lrun0 = lrun0 * rf0 + ps0;  lrun1 = lrun1 * rf1 + ps1;
        mrun0 = nm0;  mrun1 = nm1;
#pragma unroll
        for (int ni = 0; ni < 8; ni++) {
            Oc[ni][0] *= rf0; Oc[ni][1] *= rf0;
            Oc[ni][2] *= rf1; Oc[ni][3] *= rf1;
        }
        __syncwarp();   // Ps written -> read within same warp

        // O += P V : contraction over 64 kv positions
#pragma unroll
        for (int kk = 0; kk < 64; kk += 8) {
            uint32_t a0 = Ps[(slab + g) * FS + kk + tg];
            uint32_t a1 = Ps[(slab + g + 8) * FS + kk + tg];
            uint32_t a2 = Ps[(slab + g) * FS + kk + tg + 4];
            uint32_t a3 = Ps[(slab + g + 8) * FS + kk + tg + 4];
#pragma unroll
            for (int ni = 0; ni < 8; ni++) {
                uint32_t b0 = Vs[(kk + tg) * FS + ni * 8 + g];
                uint32_t b1 = Vs[(kk + tg + 4) * FS + ni * 8 + g];
                mma_tf32(Oc[ni], a0, a1, a2, a3, b0, b1);
            }
        }
    }

    // Normalize + write out: Y[b][t][h*64+d]
    float inv0 = 1.0f / lrun0, inv1 = 1.0f / lrun1;
#pragma unroll
    for (int ni = 0; ni < 8; ni++) {
        int col = h * 64 + ni * 8 + 2 * tg;
        *(float2*)&Y[((size_t)(b * TT) + row0) * CC + col] =
            make_float2(Oc[ni][0] * inv0, Oc[ni][1] * inv0);
        *(float2*)&Y[((size_t)(b * TT) + row1) * CC + col] =
            make_float2(Oc[ni][2] * inv1, Oc[ni][3] * inv1);
    }
}

// ---------------------------------------------------------------------------
extern "C" void kernel_launch(void* const* d_in, const int* in_sizes, int n_in,
                              void* d_out, int out_size)
{
    const float* x  = (const float*)d_in[0];
    const float* Wq = (const float*)d_in[1];
    const float* Wk = (const float*)d_in[2];
    const float* Wv = (const float*)d_in[3];
    const float* Wc = (const float*)d_in[4];
    const int* pos  = (const int*)d_in[5];
    float* out = (float*)d_out;

    float *qkv, *q, *k, *y, *ct, *st;
    cudaGetSymbolAddress((void**)&qkv, g_qkv);
    cudaGetSymbolAddress((void**)&q,   g_q);
    cudaGetSymbolAddress((void**)&k,   g_k);
    cudaGetSymbolAddress((void**)&y,   g_y);
    cudaGetSymbolAddress((void**)&ct,  g_ct);
    cudaGetSymbolAddress((void**)&st,  g_st);

    // Fused QKV projection (tf32 tensor cores), packed output ldc = 3072
    qkv_gemm<<<dim3(24, 32), 256>>>(x, Wq, Wk, Wv, qkv);

    // RoPE tables + apply RoPE / reshape for Q, K
    rope_tab<<<(TT * 32 + 255) / 256, 256>>>(pos, ct, st);
    rope_reshape<<<(BB * TT * (HH + HKV) * 32 + 255) / 256, 256>>>(qkv, ct, st, q, k);

    // Tensor-core flash attention
    cudaFuncSetAttribute(flash_attn_tc, cudaFuncAttributeMaxDynamicSharedMemorySize, FLASH_SMEM);
    flash_attn_tc<<<dim3(TT / 128, HH, BB), 256, FLASH_SMEM>>>(q, k, qkv + 2560, y);

    // Output projection (tf32 tensor cores)
    proj_gemm<<<dim3(16, 32), 256>>>(y, Wc, out);
}